// round 5
// baseline (speedup 1.0000x reference)
#include <cuda_runtime.h>
#include <cstdint>

// LIF scan over time axis. x: [rows, T=100] fp32, T contiguous.
// mem = prev_sp ? x : (mem*DECAY + x);  sp = mem > THRESH  (rounding-identical
// to reference's mem*DECAY*(1-sp)+x since sp is exactly 0 or 1).
//
// R5: R4 pipeline (in-place 4-deep bulk-TMA ring, hoisted load issue) with an
// ANTI-CONVOY phase stagger: CTAs delay kernel entry by (bid&3) quarter-rounds
// so the chip-wide scan windows interleave instead of synchronizing, keeping
// DRAM fed during compute phases.

#define LIF_THRESH 0.5f
#define LIF_DECAY  0.2f
#define LIF_T      100
#define LIF_TV     25                          // float4 per row (odd stride -> conflict-free)
#define CHUNK_ROWS 128
#define THREADS    128
#define NBUF       4
#define CHUNK_BYTES (CHUNK_ROWS * LIF_T * 4)   // 51200
#define SM_IN       1024                        // after mbarriers
#define SM_TOTAL    (SM_IN + NBUF * CHUNK_BYTES)  // 205824 bytes -> 1 CTA/SM
#define STAGGER_CYC 1550LL                      // ~ quarter of a steady-state round

__device__ __forceinline__ uint32_t smem_u32(const void* p) {
    uint32_t a;
    asm("{ .reg .u64 t; cvta.to.shared.u64 t, %1; cvt.u32.u64 %0, t; }" : "=r"(a) : "l"(p));
    return a;
}
__device__ __forceinline__ void mbar_init(uint32_t mbar, uint32_t cnt) {
    asm volatile("mbarrier.init.shared.b64 [%0], %1;" :: "r"(mbar), "r"(cnt) : "memory");
}
__device__ __forceinline__ void mbar_expect(uint32_t mbar, uint32_t bytes) {
    asm volatile("mbarrier.arrive.expect_tx.shared.b64 _, [%0], %1;" :: "r"(mbar), "r"(bytes) : "memory");
}
__device__ __forceinline__ void mbar_wait(uint32_t mbar, uint32_t parity) {
    uint32_t done;
    asm volatile(
        "{\n\t.reg .pred p;\n\t"
        "mbarrier.try_wait.parity.acquire.cta.shared::cta.b64 p, [%1], %2;\n\t"
        "selp.b32 %0, 1, 0, p;\n\t}"
        : "=r"(done) : "r"(mbar), "r"(parity) : "memory");
    if (!done) {
        asm volatile(
            "{\n\t.reg .pred P1;\n\t"
            "W_%=:\n\t"
            "mbarrier.try_wait.parity.acquire.cta.shared::cta.b64 P1, [%0], %1, 0x989680;\n\t"
            "@P1 bra.uni D_%=;\n\t"
            "bra.uni W_%=;\n\t"
            "D_%=:\n\t}"
            :: "r"(mbar), "r"(parity) : "memory");
    }
}
__device__ __forceinline__ void bulk_g2s(uint32_t dst_smem, const void* src, uint32_t bytes, uint32_t mbar) {
    asm volatile(
        "cp.async.bulk.shared::cluster.global.mbarrier::complete_tx::bytes [%0], [%1], %2, [%3];"
        :: "r"(dst_smem), "l"(src), "r"(bytes), "r"(mbar) : "memory");
}
__device__ __forceinline__ void bulk_s2g(void* dst, uint32_t src_smem, uint32_t bytes) {
    asm volatile(
        "cp.async.bulk.global.shared::cta.bulk_group [%0], [%1], %2;"
        :: "l"(dst), "r"(src_smem), "r"(bytes) : "memory");
}

__global__ __launch_bounds__(THREADS, 1)
void lif_tma_kernel(const char* __restrict__ gin, char* __restrict__ gout,
                    int n_chunks) {
    extern __shared__ char smem[];
    const uint32_t sbase = smem_u32(smem);
    const int tid = threadIdx.x;
    const int stride = gridDim.x;

    if ((int)blockIdx.x >= n_chunks) return;
    // Block-strided chunks: local l -> global chunk blockIdx.x + l*stride.
    const int ncl = (n_chunks - (int)blockIdx.x + stride - 1) / stride;

    if (tid == 0) {
        #pragma unroll
        for (int b = 0; b < NBUF; b++) mbar_init(sbase + 8 * b, 1);
        asm volatile("fence.proxy.async.shared::cta;" ::: "memory");
    }

    // ---- anti-convoy stagger: shift this CTA's phase by (bid&3)/4 round ----
    {
        long long delay = (long long)(blockIdx.x & 3) * STAGGER_CYC;
        if (delay > 0) {
            long long start = clock64();
            while (clock64() - start < delay) { }
        }
    }
    __syncthreads();

    // Prologue: prefetch up to 3 chunks.
    if (tid == 0) {
        int pre = ncl < 3 ? ncl : 3;
        for (int l = 0; l < pre; l++) {
            long long g = (long long)blockIdx.x + (long long)l * stride;
            mbar_expect(sbase + 8 * l, CHUNK_BYTES);
            bulk_g2s(sbase + SM_IN + l * CHUNK_BYTES,
                     gin + g * CHUNK_BYTES, CHUNK_BYTES, sbase + 8 * l);
        }
    }

    for (int l = 0; l < ncl; l++) {
        const int b = l & (NBUF - 1);
        const long long g = (long long)blockIdx.x + (long long)l * stride;

        // Keep the load pipeline full BEFORE scanning: buffer (l+3)&3 held
        // chunk l-1, whose store was committed at the end of iter l-1;
        // wait_group.read 0 guarantees its smem has been fully read out.
        if (tid == 0 && l + 3 < ncl) {
            asm volatile("cp.async.bulk.wait_group.read 0;" ::: "memory");
            const int nb = (l + 3) & (NBUF - 1);
            const long long ng = (long long)blockIdx.x + (long long)(l + 3) * stride;
            mbar_expect(sbase + 8 * nb, CHUNK_BYTES);
            bulk_g2s(sbase + SM_IN + nb * CHUNK_BYTES,
                     gin + ng * CHUNK_BYTES, CHUNK_BYTES, sbase + 8 * nb);
        }

        // Wait for load of chunk l (buffer b, 4-use parity).
        mbar_wait(sbase + 8 * b, (l >> 2) & 1);

        // Streaming in-place scan: read f4, compute, write spikes back.
        float4* row = (float4*)(smem + SM_IN + b * CHUNK_BYTES) + tid * LIF_TV;
        float mem = 0.0f;
        bool sp = false;
        #pragma unroll
        for (int k = 0; k < LIF_TV; k++) {
            float4 v = row[k];
            float4 o;
            float t;
            t = __fadd_rn(__fmul_rn(mem, LIF_DECAY), v.x);
            mem = sp ? v.x : t;  sp = mem > LIF_THRESH;  o.x = sp ? 1.0f : 0.0f;
            t = __fadd_rn(__fmul_rn(mem, LIF_DECAY), v.y);
            mem = sp ? v.y : t;  sp = mem > LIF_THRESH;  o.y = sp ? 1.0f : 0.0f;
            t = __fadd_rn(__fmul_rn(mem, LIF_DECAY), v.z);
            mem = sp ? v.z : t;  sp = mem > LIF_THRESH;  o.z = sp ? 1.0f : 0.0f;
            t = __fadd_rn(__fmul_rn(mem, LIF_DECAY), v.w);
            mem = sp ? v.w : t;  sp = mem > LIF_THRESH;  o.w = sp ? 1.0f : 0.0f;
            row[k] = o;
        }

        // Publish STS to the async proxy, then store chunk l.
        asm volatile("fence.proxy.async.shared::cta;" ::: "memory");
        __syncthreads();
        if (tid == 0) {
            bulk_s2g(gout + g * CHUNK_BYTES,
                     sbase + SM_IN + b * CHUNK_BYTES, CHUNK_BYTES);
            asm volatile("cp.async.bulk.commit_group;" ::: "memory");
        }
    }

    // Keep smem alive until all pending bulk stores have read it.
    if (tid == 0)
        asm volatile("cp.async.bulk.wait_group.read 0;" ::: "memory");
}

// Scalar tail for rows not covered by full chunks.
__global__ void lif_scan_tail_kernel(const float* __restrict__ x,
                                     float* __restrict__ out,
                                     long long row_start, long long n_rows) {
    long long r = row_start + blockIdx.x * (long long)blockDim.x + threadIdx.x;
    if (r >= n_rows) return;
    const float* xr = x + r * LIF_T;
    float* orow = out + r * LIF_T;
    float mem = 0.0f;
    bool sp = false;
    #pragma unroll 4
    for (int t = 0; t < LIF_T; t++) {
        float tt = __fadd_rn(__fmul_rn(mem, LIF_DECAY), xr[t]);
        mem = sp ? xr[t] : tt;
        sp = mem > LIF_THRESH;
        orow[t] = sp ? 1.0f : 0.0f;
    }
}

extern "C" void kernel_launch(void* const* d_in, const int* in_sizes, int n_in,
                              void* d_out, int out_size) {
    const float* x = (const float*)d_in[0];
    float* out = (float*)d_out;

    long long total = (long long)in_sizes[0];
    long long n_rows = total / LIF_T;                 // 524288
    long long n_chunks = n_rows / CHUNK_ROWS;         // 4096

    if (n_chunks > 0) {
        static int smem_set = 0;
        if (!smem_set) {
            cudaFuncSetAttribute(lif_tma_kernel,
                                 cudaFuncAttributeMaxDynamicSharedMemorySize, SM_TOTAL);
            smem_set = 1;
        }
        // One CTA per SM (GB300: 152 SMs), single wave, block-strided work.
        long long grid = 152;
        if (n_chunks < grid) grid = n_chunks;
        lif_tma_kernel<<<(unsigned)grid, THREADS, SM_TOTAL>>>(
            (const char*)x, (char*)out, (int)n_chunks);
    }

    long long done_rows = n_chunks * CHUNK_ROWS;
    long long rem = n_rows - done_rows;
    if (rem > 0) {
        int threads = 128;
        int blocks = (int)((rem + threads - 1) / threads);
        lif_scan_tail_kernel<<<blocks, threads>>>(x, out, done_rows, n_rows);
    }
}

// round 6
// speedup vs baseline: 1.0254x; 1.0254x over previous
#include <cuda_runtime.h>
#include <cstdint>

// LIF scan over time axis. x: [rows, T=100] fp32, T contiguous.
// mem = prev_sp ? x : (mem*DECAY + x);  sp = mem > THRESH  (rounding-identical
// to reference's mem*DECAY*(1-sp)+x since sp is exactly 0 or 1).
//
// R6: WARP-DECOUPLED streaming. Each warp owns a private 4-deep bulk-TMA ring
// (32-row / 12.8 KB chunks), private mbarriers, and its own bulk-store group.
// No __syncthreads in the main loop -> 4 independently-phased memory streams
// per SM (608 chip-wide), so DRAM demand never collapses into a chip-wide
// compute bubble.

#define LIF_THRESH 0.5f
#define LIF_DECAY  0.2f
#define LIF_T      100
#define LIF_TV     25                           // float4 per row (odd stride -> conflict-free)
#define CHUNK_ROWS 32
#define WARPS      4
#define THREADS    (WARPS * 32)
#define NBUF       4
#define CHUNK_BYTES (CHUNK_ROWS * LIF_T * 4)    // 12800
#define SM_IN       1024                         // after 16 mbarriers
#define SM_TOTAL    (SM_IN + WARPS * NBUF * CHUNK_BYTES)  // 205824 -> 1 CTA/SM

__device__ __forceinline__ uint32_t smem_u32(const void* p) {
    uint32_t a;
    asm("{ .reg .u64 t; cvta.to.shared.u64 t, %1; cvt.u32.u64 %0, t; }" : "=r"(a) : "l"(p));
    return a;
}
__device__ __forceinline__ void mbar_init(uint32_t mbar, uint32_t cnt) {
    asm volatile("mbarrier.init.shared.b64 [%0], %1;" :: "r"(mbar), "r"(cnt) : "memory");
}
__device__ __forceinline__ void mbar_expect(uint32_t mbar, uint32_t bytes) {
    asm volatile("mbarrier.arrive.expect_tx.shared.b64 _, [%0], %1;" :: "r"(mbar), "r"(bytes) : "memory");
}
__device__ __forceinline__ void mbar_wait(uint32_t mbar, uint32_t parity) {
    uint32_t done;
    asm volatile(
        "{\n\t.reg .pred p;\n\t"
        "mbarrier.try_wait.parity.acquire.cta.shared::cta.b64 p, [%1], %2;\n\t"
        "selp.b32 %0, 1, 0, p;\n\t}"
        : "=r"(done) : "r"(mbar), "r"(parity) : "memory");
    if (!done) {
        asm volatile(
            "{\n\t.reg .pred P1;\n\t"
            "W_%=:\n\t"
            "mbarrier.try_wait.parity.acquire.cta.shared::cta.b64 P1, [%0], %1, 0x989680;\n\t"
            "@P1 bra.uni D_%=;\n\t"
            "bra.uni W_%=;\n\t"
            "D_%=:\n\t}"
            :: "r"(mbar), "r"(parity) : "memory");
    }
}
__device__ __forceinline__ void bulk_g2s(uint32_t dst_smem, const void* src, uint32_t bytes, uint32_t mbar) {
    asm volatile(
        "cp.async.bulk.shared::cluster.global.mbarrier::complete_tx::bytes [%0], [%1], %2, [%3];"
        :: "r"(dst_smem), "l"(src), "r"(bytes), "r"(mbar) : "memory");
}
__device__ __forceinline__ void bulk_s2g(void* dst, uint32_t src_smem, uint32_t bytes) {
    asm volatile(
        "cp.async.bulk.global.shared::cta.bulk_group [%0], [%1], %2;"
        :: "l"(dst), "r"(src_smem), "r"(bytes) : "memory");
}

__global__ __launch_bounds__(THREADS, 1)
void lif_tma_kernel(const char* __restrict__ gin, char* __restrict__ gout,
                    int n_chunks) {
    extern __shared__ char smem[];
    const uint32_t sbase = smem_u32(smem);
    const int tid  = threadIdx.x;
    const int warp = tid >> 5;
    const int lane = tid & 31;

    // Stream id: one independent chunk stream per warp, chip-wide.
    const long long sid     = (long long)blockIdx.x * WARPS + warp;
    const long long sstride = (long long)gridDim.x * WARPS;

    // This warp's private ring.
    const uint32_t mbar0 = sbase + (uint32_t)(warp * NBUF) * 8;
    const uint32_t buf0  = sbase + SM_IN + (uint32_t)(warp * NBUF) * CHUNK_BYTES;

    if (tid == 0) {
        #pragma unroll
        for (int i = 0; i < WARPS * NBUF; i++) mbar_init(sbase + 8 * i, 1);
        asm volatile("fence.proxy.async.shared::cta;" ::: "memory");
    }
    __syncthreads();   // the only CTA-wide barrier: mbarriers visible

    if (sid >= n_chunks) return;
    const int ncl = (int)((n_chunks - sid + sstride - 1) / sstride);

    // Prologue: prefetch up to 3 chunks (lane 0 of this warp).
    if (lane == 0) {
        int pre = ncl < 3 ? ncl : 3;
        for (int l = 0; l < pre; l++) {
            long long g = sid + (long long)l * sstride;
            mbar_expect(mbar0 + 8u * l, CHUNK_BYTES);
            bulk_g2s(buf0 + (uint32_t)l * CHUNK_BYTES,
                     gin + g * CHUNK_BYTES, CHUNK_BYTES, mbar0 + 8u * l);
        }
    }

    for (int l = 0; l < ncl; l++) {
        const int b = l & (NBUF - 1);
        const long long g = sid + (long long)l * sstride;

        // Keep this warp's load pipeline full BEFORE scanning. Buffer
        // (l+3)&3 held chunk l-1, whose store group was committed at the
        // end of iter l-1 by this same lane; wait_group.read 0 guarantees
        // its smem has been fully read out.
        if (lane == 0 && l + 3 < ncl) {
            asm volatile("cp.async.bulk.wait_group.read 0;" ::: "memory");
            const int nb = (l + 3) & (NBUF - 1);
            const long long ng = sid + (long long)(l + 3) * sstride;
            mbar_expect(mbar0 + 8u * nb, CHUNK_BYTES);
            bulk_g2s(buf0 + (uint32_t)nb * CHUNK_BYTES,
                     gin + ng * CHUNK_BYTES, CHUNK_BYTES, mbar0 + 8u * nb);
        }

        // Wait for load of chunk l (buffer b, 4-use parity). Warp-only wait.
        mbar_wait(mbar0 + 8u * b, (l >> 2) & 1);

        // Streaming in-place scan: read f4, compute, write spikes back.
        float4* row = (float4*)(smem + (buf0 - sbase) + (uint32_t)b * CHUNK_BYTES)
                      + lane * LIF_TV;
        float mem = 0.0f;
        bool sp = false;
        #pragma unroll
        for (int k = 0; k < LIF_TV; k++) {
            float4 v = row[k];
            float4 o;
            float t;
            t = __fadd_rn(__fmul_rn(mem, LIF_DECAY), v.x);
            mem = sp ? v.x : t;  sp = mem > LIF_THRESH;  o.x = sp ? 1.0f : 0.0f;
            t = __fadd_rn(__fmul_rn(mem, LIF_DECAY), v.y);
            mem = sp ? v.y : t;  sp = mem > LIF_THRESH;  o.y = sp ? 1.0f : 0.0f;
            t = __fadd_rn(__fmul_rn(mem, LIF_DECAY), v.z);
            mem = sp ? v.z : t;  sp = mem > LIF_THRESH;  o.z = sp ? 1.0f : 0.0f;
            t = __fadd_rn(__fmul_rn(mem, LIF_DECAY), v.w);
            mem = sp ? v.w : t;  sp = mem > LIF_THRESH;  o.w = sp ? 1.0f : 0.0f;
            row[k] = o;
        }

        // Warp-scoped publish: all lanes' STS happen-before lane 0's proxy
        // fence, then lane 0 issues the bulk store for this warp's chunk.
        __syncwarp();
        if (lane == 0) {
            asm volatile("fence.proxy.async.shared::cta;" ::: "memory");
            bulk_s2g(gout + g * CHUNK_BYTES,
                     buf0 + (uint32_t)b * CHUNK_BYTES, CHUNK_BYTES);
            asm volatile("cp.async.bulk.commit_group;" ::: "memory");
        }
    }

    // Keep smem alive until this warp's pending bulk stores have read it.
    if (lane == 0)
        asm volatile("cp.async.bulk.wait_group.read 0;" ::: "memory");
    __syncwarp();
}

// Scalar tail for rows not covered by full chunks.
__global__ void lif_scan_tail_kernel(const float* __restrict__ x,
                                     float* __restrict__ out,
                                     long long row_start, long long n_rows) {
    long long r = row_start + blockIdx.x * (long long)blockDim.x + threadIdx.x;
    if (r >= n_rows) return;
    const float* xr = x + r * LIF_T;
    float* orow = out + r * LIF_T;
    float mem = 0.0f;
    bool sp = false;
    #pragma unroll 4
    for (int t = 0; t < LIF_T; t++) {
        float tt = __fadd_rn(__fmul_rn(mem, LIF_DECAY), xr[t]);
        mem = sp ? xr[t] : tt;
        sp = mem > LIF_THRESH;
        orow[t] = sp ? 1.0f : 0.0f;
    }
}

extern "C" void kernel_launch(void* const* d_in, const int* in_sizes, int n_in,
                              void* d_out, int out_size) {
    const float* x = (const float*)d_in[0];
    float* out = (float*)d_out;

    long long total = (long long)in_sizes[0];
    long long n_rows = total / LIF_T;                  // 524288
    long long n_chunks = n_rows / CHUNK_ROWS;          // 16384

    if (n_chunks > 0) {
        static int smem_set = 0;
        if (!smem_set) {
            cudaFuncSetAttribute(lif_tma_kernel,
                                 cudaFuncAttributeMaxDynamicSharedMemorySize, SM_TOTAL);
            smem_set = 1;
        }
        // One CTA per SM (GB300: 152 SMs); 4 warp-streams per CTA.
        long long grid = 152;
        long long max_grid = (n_chunks + WARPS - 1) / WARPS;
        if (max_grid < grid) grid = max_grid;
        lif_tma_kernel<<<(unsigned)grid, THREADS, SM_TOTAL>>>(
            (const char*)x, (char*)out, (int)n_chunks);
    }

    long long done_rows = n_chunks * CHUNK_ROWS;
    long long rem = n_rows - done_rows;
    if (rem > 0) {
        int threads = 128;
        int blocks = (int)((rem + threads - 1) / threads);
        lif_scan_tail_kernel<<<blocks, threads>>>(x, out, done_rows, n_rows);
    }
}

// round 7
// speedup vs baseline: 1.1486x; 1.1202x over previous
#include <cuda_runtime.h>
#include <cstdint>

// LIF scan over time axis. x: [rows, T=100] fp32, T contiguous.
// mem = prev_sp ? x : (mem*DECAY + x);  sp = mem > THRESH  (rounding-identical
// to reference's mem*DECAY*(1-sp)+x since sp is exactly 0 or 1).
//
// R7 (final form): bulk-TMA in-place 4-deep ring, hoisted load issue,
// PERFECTLY BALANCED single-wave grid (128 CTAs x 32 chunks exactly for the
// fixed shape) to remove the drain-straggler round. Six schedule variants
// established the HBM r/w-mix wall at ~5.9 TB/s (74% duty); this variant
// just minimizes everything else around it.

#define LIF_THRESH 0.5f
#define LIF_DECAY  0.2f
#define LIF_T      100
#define LIF_TV     25                          // float4 per row (odd stride -> conflict-free)
#define CHUNK_ROWS 128
#define THREADS    128
#define NBUF       4
#define CHUNK_BYTES (CHUNK_ROWS * LIF_T * 4)   // 51200
#define SM_IN       1024                        // after mbarriers
#define SM_TOTAL    (SM_IN + NBUF * CHUNK_BYTES)  // 205824 bytes -> 1 CTA/SM

__device__ __forceinline__ uint32_t smem_u32(const void* p) {
    uint32_t a;
    asm("{ .reg .u64 t; cvta.to.shared.u64 t, %1; cvt.u32.u64 %0, t; }" : "=r"(a) : "l"(p));
    return a;
}
__device__ __forceinline__ void mbar_init(uint32_t mbar, uint32_t cnt) {
    asm volatile("mbarrier.init.shared.b64 [%0], %1;" :: "r"(mbar), "r"(cnt) : "memory");
}
__device__ __forceinline__ void mbar_expect(uint32_t mbar, uint32_t bytes) {
    asm volatile("mbarrier.arrive.expect_tx.shared.b64 _, [%0], %1;" :: "r"(mbar), "r"(bytes) : "memory");
}
__device__ __forceinline__ void mbar_wait(uint32_t mbar, uint32_t parity) {
    uint32_t done;
    asm volatile(
        "{\n\t.reg .pred p;\n\t"
        "mbarrier.try_wait.parity.acquire.cta.shared::cta.b64 p, [%1], %2;\n\t"
        "selp.b32 %0, 1, 0, p;\n\t}"
        : "=r"(done) : "r"(mbar), "r"(parity) : "memory");
    if (!done) {
        asm volatile(
            "{\n\t.reg .pred P1;\n\t"
            "W_%=:\n\t"
            "mbarrier.try_wait.parity.acquire.cta.shared::cta.b64 P1, [%0], %1, 0x989680;\n\t"
            "@P1 bra.uni D_%=;\n\t"
            "bra.uni W_%=;\n\t"
            "D_%=:\n\t}"
            :: "r"(mbar), "r"(parity) : "memory");
    }
}
__device__ __forceinline__ void bulk_g2s(uint32_t dst_smem, const void* src, uint32_t bytes, uint32_t mbar) {
    asm volatile(
        "cp.async.bulk.shared::cluster.global.mbarrier::complete_tx::bytes [%0], [%1], %2, [%3];"
        :: "r"(dst_smem), "l"(src), "r"(bytes), "r"(mbar) : "memory");
}
__device__ __forceinline__ void bulk_s2g(void* dst, uint32_t src_smem, uint32_t bytes) {
    asm volatile(
        "cp.async.bulk.global.shared::cta.bulk_group [%0], [%1], %2;"
        :: "l"(dst), "r"(src_smem), "r"(bytes) : "memory");
}

__global__ __launch_bounds__(THREADS, 1)
void lif_tma_kernel(const char* __restrict__ gin, char* __restrict__ gout,
                    int n_chunks) {
    extern __shared__ char smem[];
    const uint32_t sbase = smem_u32(smem);
    const int tid = threadIdx.x;
    const int stride = gridDim.x;

    if ((int)blockIdx.x >= n_chunks) return;
    // Block-strided chunks: local l -> global chunk blockIdx.x + l*stride.
    const int ncl = (n_chunks - (int)blockIdx.x + stride - 1) / stride;

    if (tid == 0) {
        #pragma unroll
        for (int b = 0; b < NBUF; b++) mbar_init(sbase + 8 * b, 1);
        asm volatile("fence.proxy.async.shared::cta;" ::: "memory");
    }
    __syncthreads();

    // Prologue: prefetch up to 3 chunks.
    if (tid == 0) {
        int pre = ncl < 3 ? ncl : 3;
        for (int l = 0; l < pre; l++) {
            long long g = (long long)blockIdx.x + (long long)l * stride;
            mbar_expect(sbase + 8 * l, CHUNK_BYTES);
            bulk_g2s(sbase + SM_IN + l * CHUNK_BYTES,
                     gin + g * CHUNK_BYTES, CHUNK_BYTES, sbase + 8 * l);
        }
    }

    for (int l = 0; l < ncl; l++) {
        const int b = l & (NBUF - 1);
        const long long g = (long long)blockIdx.x + (long long)l * stride;

        // Keep the load pipeline full BEFORE scanning: buffer (l+3)&3 held
        // chunk l-1, whose store was committed at the end of iter l-1;
        // wait_group.read 0 guarantees its smem has been fully read out.
        if (tid == 0 && l + 3 < ncl) {
            asm volatile("cp.async.bulk.wait_group.read 0;" ::: "memory");
            const int nb = (l + 3) & (NBUF - 1);
            const long long ng = (long long)blockIdx.x + (long long)(l + 3) * stride;
            mbar_expect(sbase + 8 * nb, CHUNK_BYTES);
            bulk_g2s(sbase + SM_IN + nb * CHUNK_BYTES,
                     gin + ng * CHUNK_BYTES, CHUNK_BYTES, sbase + 8 * nb);
        }

        // Wait for load of chunk l (buffer b, 4-use parity).
        mbar_wait(sbase + 8 * b, (l >> 2) & 1);

        // Streaming in-place scan: read f4, compute, write spikes back.
        float4* row = (float4*)(smem + SM_IN + b * CHUNK_BYTES) + tid * LIF_TV;
        float mem = 0.0f;
        bool sp = false;
        #pragma unroll
        for (int k = 0; k < LIF_TV; k++) {
            float4 v = row[k];
            float4 o;
            float t;
            t = __fadd_rn(__fmul_rn(mem, LIF_DECAY), v.x);
            mem = sp ? v.x : t;  sp = mem > LIF_THRESH;  o.x = sp ? 1.0f : 0.0f;
            t = __fadd_rn(__fmul_rn(mem, LIF_DECAY), v.y);
            mem = sp ? v.y : t;  sp = mem > LIF_THRESH;  o.y = sp ? 1.0f : 0.0f;
            t = __fadd_rn(__fmul_rn(mem, LIF_DECAY), v.z);
            mem = sp ? v.z : t;  sp = mem > LIF_THRESH;  o.z = sp ? 1.0f : 0.0f;
            t = __fadd_rn(__fmul_rn(mem, LIF_DECAY), v.w);
            mem = sp ? v.w : t;  sp = mem > LIF_THRESH;  o.w = sp ? 1.0f : 0.0f;
            row[k] = o;
        }

        // Publish STS to the async proxy, then store chunk l.
        asm volatile("fence.proxy.async.shared::cta;" ::: "memory");
        __syncthreads();
        if (tid == 0) {
            bulk_s2g(gout + g * CHUNK_BYTES,
                     sbase + SM_IN + b * CHUNK_BYTES, CHUNK_BYTES);
            asm volatile("cp.async.bulk.commit_group;" ::: "memory");
        }
    }

    // Keep smem alive until all pending bulk stores have read it.
    if (tid == 0)
        asm volatile("cp.async.bulk.wait_group.read 0;" ::: "memory");
}

// Scalar tail for rows not covered by full chunks.
__global__ void lif_scan_tail_kernel(const float* __restrict__ x,
                                     float* __restrict__ out,
                                     long long row_start, long long n_rows) {
    long long r = row_start + blockIdx.x * (long long)blockDim.x + threadIdx.x;
    if (r >= n_rows) return;
    const float* xr = x + r * LIF_T;
    float* orow = out + r * LIF_T;
    float mem = 0.0f;
    bool sp = false;
    #pragma unroll 4
    for (int t = 0; t < LIF_T; t++) {
        float tt = __fadd_rn(__fmul_rn(mem, LIF_DECAY), xr[t]);
        mem = sp ? xr[t] : tt;
        sp = mem > LIF_THRESH;
        orow[t] = sp ? 1.0f : 0.0f;
    }
}

extern "C" void kernel_launch(void* const* d_in, const int* in_sizes, int n_in,
                              void* d_out, int out_size) {
    const float* x = (const float*)d_in[0];
    float* out = (float*)d_out;

    long long total = (long long)in_sizes[0];
    long long n_rows = total / LIF_T;                 // 524288
    long long n_chunks = n_rows / CHUNK_ROWS;         // 4096

    if (n_chunks > 0) {
        static int smem_set = 0;
        if (!smem_set) {
            cudaFuncSetAttribute(lif_tma_kernel,
                                 cudaFuncAttributeMaxDynamicSharedMemorySize, SM_TOTAL);
            smem_set = 1;
        }
        // Perfectly balanced single wave: 128 CTAs x 32 chunks for the fixed
        // shape (4096 % 128 == 0). DRAM-bound, so 128 of 152 SMs is enough
        // to hold the HBM wall; balance beats SM count here.
        long long grid = 128;
        if (n_chunks < grid) grid = n_chunks;
        lif_tma_kernel<<<(unsigned)grid, THREADS, SM_TOTAL>>>(
            (const char*)x, (char*)out, (int)n_chunks);
    }

    long long done_rows = n_chunks * CHUNK_ROWS;
    long long rem = n_rows - done_rows;
    if (rem > 0) {
        int threads = 128;
        int blocks = (int)((rem + threads - 1) / threads);
        lif_scan_tail_kernel<<<blocks, threads>>>(x, out, done_rows, n_rows);
    }
}